// round 14
// baseline (speedup 1.0000x reference)
#include <cuda_runtime.h>
#include <cuda_fp16.h>
#include <cuda_bf16.h>

#define B_  131072
#define DD  784
#define HID 256
#define MD  16
#define RS  80   // padded smem row stride (bytes) for a 32-half k-row

__device__ __align__(16) __half g_W1t_hi[HID * 832];
__device__ __align__(16) __half g_W1t_lo[HID * 832];
__device__ __align__(16) __half g_W2t_hi[HID * HID];
__device__ __align__(16) __half g_W2t_lo[HID * HID];
__device__ __align__(16) __half g_Wpt_hi[MD * 832];
__device__ __align__(16) __half g_Wpt_lo[MD * 832];
__device__ __align__(16) __nv_bfloat16 g_Wlb_hi[DD * MD];  // Wl^T [784][16] bf16 hi
__device__ __align__(16) __nv_bfloat16 g_Wlb_lo[DD * MD];
__device__ __align__(16) __nv_bfloat16 g_y_hi[(size_t)B_ * MD];
__device__ __align__(16) __nv_bfloat16 g_y_lo[(size_t)B_ * MD];
__device__ __align__(16) __half g_h_hi[(size_t)B_ * HID];
__device__ __align__(16) __half g_h_lo[(size_t)B_ * HID];
__device__ __align__(16) float g_xi[(size_t)B_ * MD];

__device__ __forceinline__ unsigned su32(const void* p) {
    unsigned a;
    asm("{ .reg .u64 t; cvta.to.shared.u64 t, %1; cvt.u32.u64 %0, t; }" : "=r"(a) : "l"(p));
    return a;
}
__device__ __forceinline__ void ldm4(unsigned (&r)[4], unsigned addr) {
    asm volatile("ldmatrix.sync.aligned.m8n8.x4.shared.b16 {%0,%1,%2,%3}, [%4];"
                 : "=r"(r[0]), "=r"(r[1]), "=r"(r[2]), "=r"(r[3]) : "r"(addr));
}
__device__ __forceinline__ void ldm2(unsigned (&r)[2], unsigned addr) {
    asm volatile("ldmatrix.sync.aligned.m8n8.x2.shared.b16 {%0,%1}, [%2];"
                 : "=r"(r[0]), "=r"(r[1]) : "r"(addr));
}
__device__ __forceinline__ void mma16816(float (&c)[4], const unsigned (&a)[4],
                                         unsigned b0, unsigned b1) {
    asm volatile("mma.sync.aligned.m16n8k16.row.col.f32.f16.f16.f32 "
                 "{%0,%1,%2,%3}, {%4,%5,%6,%7}, {%8,%9}, {%0,%1,%2,%3};"
                 : "+f"(c[0]), "+f"(c[1]), "+f"(c[2]), "+f"(c[3])
                 : "r"(a[0]), "r"(a[1]), "r"(a[2]), "r"(a[3]), "r"(b0), "r"(b1));
}
__device__ __forceinline__ void mma16816bf(float (&c)[4], const unsigned (&a)[4],
                                           unsigned b0, unsigned b1) {
    asm volatile("mma.sync.aligned.m16n8k16.row.col.f32.bf16.bf16.f32 "
                 "{%0,%1,%2,%3}, {%4,%5,%6,%7}, {%8,%9}, {%0,%1,%2,%3};"
                 : "+f"(c[0]), "+f"(c[1]), "+f"(c[2]), "+f"(c[3])
                 : "r"(a[0]), "r"(a[1]), "r"(a[2]), "r"(a[3]), "r"(b0), "r"(b1));
}
__device__ __forceinline__ void cpa16(unsigned s, const void* g) {
    asm volatile("cp.async.cg.shared.global [%0], [%1], 16;" :: "r"(s), "l"(g));
}
#define CP_COMMIT() asm volatile("cp.async.commit_group;" ::: "memory")
#define CP_WAIT0()  asm volatile("cp.async.wait_group 0;" ::: "memory")

__device__ __forceinline__ unsigned pk(__half a, __half b) {
    return (unsigned)__half_as_ushort(a) | ((unsigned)__half_as_ushort(b) << 16);
}
__device__ __forceinline__ void split(float v, __half& h, __half& l) {
    h = __float2half_rn(v);
    l = __float2half_rn(v - __half2float(h));
}

// prep: W^T fp16 hi/lo (zero-padded K); Wl^T bf16 hi/lo
__global__ void prep_kernel(const float* __restrict__ W1, const float* __restrict__ W2,
                            const float* __restrict__ Wp, const float* __restrict__ Wl) {
    int idx = blockIdx.x * 256 + threadIdx.x;
    const int T1 = HID * 832, T2 = HID * HID, T3 = MD * 832, T4 = DD * MD;
    if (idx < T1) {
        int n = idx / 832, k = idx - n * 832;
        float v = (k < DD) ? W1[(size_t)k * HID + n] : 0.0f;
        __half h, l; split(v, h, l);
        g_W1t_hi[idx] = h; g_W1t_lo[idx] = l;
    } else if (idx < T1 + T2) {
        int j = idx - T1, n = j >> 8, k = j & 255;
        float v = W2[(size_t)k * HID + n];
        __half h, l; split(v, h, l);
        g_W2t_hi[j] = h; g_W2t_lo[j] = l;
    } else if (idx < T1 + T2 + T3) {
        int j = idx - T1 - T2, n = j / 832, k = j - n * 832;
        float v = (k < DD) ? Wp[(size_t)k * MD + n] : 0.0f;
        __half h, l; split(v, h, l);
        g_Wpt_hi[j] = h; g_Wpt_lo[j] = l;
    } else if (idx < T1 + T2 + T3 + T4) {
        int j = idx - T1 - T2 - T3, col = j >> 4, k = j & 15;
        float v = Wl[(size_t)k * DD + col];
        __nv_bfloat16 h = __float2bfloat16(v);
        g_Wlb_hi[j] = h;
        g_Wlb_lo[j] = __float2bfloat16(v - __bfloat162float(h));
    }
}

// smem layout per stage (51200 B): A hi 5120 | A lo 5120 | B hi 20480 | B lo 20480
#define AHI(s) ((s) * 51200)
#define ALO(s) ((s) * 51200 + 5120)
#define BHI(s) ((s) * 51200 + 10240)
#define BLO(s) ((s) * 51200 + 30720)
#define PHI(s) (102400 + (s) * 2560)
#define PLO(s) (102400 + (s) * 2560 + 1280)
#define SMG1 107520
#define SMG2 102400

// ---------- GEMM1 merged: h = relu(x@W1+b1), xi = x@Wp+bp. M64 N256 k32 -----
__global__ __launch_bounds__(256, 2)
void gemm1_m(const float* __restrict__ X, const float* __restrict__ b1v,
             const float* __restrict__ bpv) {
    extern __shared__ char smc[];
    const unsigned sb = su32(smc);
    const int tid = threadIdx.x, lane = tid & 31, w = tid >> 5;
    const int wm = w >> 2, wn = w & 3;
    const int t8 = lane >> 3, r8 = lane & 7;
    const size_t row0 = (size_t)blockIdx.x * 64;

    float acc[2][8][4] = {};
    float axi[2][2][4] = {};
    float xr[8];
    const int ar = tid >> 2, av = tid & 3;

    auto ldgA = [&](int c) {
        int col = c * 32 + av * 8;
        if (col < DD) {
            *(float4*)xr       = *(const float4*)(X + (row0 + ar) * DD + col);
            *(float4*)(xr + 4) = *(const float4*)(X + (row0 + ar) * DD + col + 4);
        } else {
#pragma unroll
            for (int i = 0; i < 8; i++) xr[i] = 0.0f;
        }
    };
    auto stsA = [&](int s) {
        __half h[8], l[8];
#pragma unroll
        for (int i = 0; i < 8; i++) split(xr[i], h[i], l[i]);
        uint4 vh, vl;
        vh.x = pk(h[0], h[1]); vh.y = pk(h[2], h[3]); vh.z = pk(h[4], h[5]); vh.w = pk(h[6], h[7]);
        vl.x = pk(l[0], l[1]); vl.y = pk(l[2], l[3]); vl.z = pk(l[4], l[5]); vl.w = pk(l[6], l[7]);
        *(uint4*)(smc + AHI(s) + ar * RS + av * 16) = vh;
        *(uint4*)(smc + ALO(s) + ar * RS + av * 16) = vl;
    };
    auto cpaB = [&](int c, int s) {
#pragma unroll
        for (int i = 0; i < 4; i++) {
            int j = tid + i * 256, r = j >> 2, v = j & 3;
            const size_t src = (size_t)r * 832 + c * 32 + v * 8;
            cpa16(sb + BHI(s) + r * RS + v * 16, g_W1t_hi + src);
            cpa16(sb + BLO(s) + r * RS + v * 16, g_W1t_lo + src);
        }
        if (tid < 128) {
            int r = (tid & 63) >> 2, v = tid & 3;
            const size_t src = (size_t)r * 832 + c * 32 + v * 8;
            if (tid < 64) cpa16(sb + PHI(s) + r * RS + v * 16, g_Wpt_hi + src);
            else          cpa16(sb + PLO(s) + r * RS + v * 16, g_Wpt_lo + src);
        }
    };

    ldgA(0); stsA(0); cpaB(0, 0);
    CP_COMMIT(); CP_WAIT0();
    __syncthreads();

    for (int c = 0; c < 26; c++) {
        const int s = c & 1;
        const bool more = (c + 1 < 26);
        if (more) { ldgA(c + 1); cpaB(c + 1, s ^ 1); CP_COMMIT(); }
#pragma unroll
        for (int ks = 0; ks < 2; ks++) {
            const int u = ks * 2 + (t8 >> 1);
            unsigned ah[2][4], al[2][4];
#pragma unroll
            for (int mi = 0; mi < 2; mi++) {
                int m = wm * 32 + mi * 16 + (t8 & 1) * 8 + r8;
                ldm4(ah[mi], sb + AHI(s) + m * RS + u * 16);
                ldm4(al[mi], sb + ALO(s) + m * RS + u * 16);
            }
#pragma unroll
            for (int ng = 0; ng < 4; ng++) {
                unsigned bh[4], bo[4];
                int n = wn * 64 + ng * 16 + (t8 & 1) * 8 + r8;
                ldm4(bh, sb + BHI(s) + n * RS + u * 16);
                ldm4(bo, sb + BLO(s) + n * RS + u * 16);
#pragma unroll
                for (int mi = 0; mi < 2; mi++)
#pragma unroll
                    for (int o = 0; o < 2; o++) {
                        float (&A_)[4] = acc[mi][ng * 2 + o];
                        mma16816(A_, ah[mi], bh[o], bh[o + 2]);
                        mma16816(A_, ah[mi], bo[o], bo[o + 2]);
                        mma16816(A_, al[mi], bh[o], bh[o + 2]);
                    }
            }
            if (wn == 0) {
                unsigned ph[4], po[4];
                int n = (t8 & 1) * 8 + r8;
                ldm4(ph, sb + PHI(s) + n * RS + u * 16);
                ldm4(po, sb + PLO(s) + n * RS + u * 16);
#pragma unroll
                for (int mi = 0; mi < 2; mi++)
#pragma unroll
                    for (int nj = 0; nj < 2; nj++) {
                        mma16816(axi[mi][nj], ah[mi], ph[nj], ph[nj + 2]);
                        mma16816(axi[mi][nj], ah[mi], po[nj], po[nj + 2]);
                        mma16816(axi[mi][nj], al[mi], ph[nj], ph[nj + 2]);
                    }
            }
        }
        if (more) stsA(s ^ 1);
        CP_WAIT0();
        __syncthreads();
    }

    const int rq = lane >> 2, cq = (lane & 3) * 2;
#pragma unroll
    for (int mi = 0; mi < 2; mi++)
#pragma unroll
        for (int nj = 0; nj < 8; nj++) {
            const int colg = wn * 64 + nj * 8 + cq;
            const float bb0 = __ldg(b1v + colg), bb1 = __ldg(b1v + colg + 1);
#pragma unroll
            for (int hr = 0; hr < 2; hr++) {
                const int r = wm * 32 + mi * 16 + rq + hr * 8;
                float v0 = fmaxf(acc[mi][nj][hr * 2 + 0] + bb0, 0.0f);
                float v1 = fmaxf(acc[mi][nj][hr * 2 + 1] + bb1, 0.0f);
                __half h0, l0, h1, l1;
                split(v0, h0, l0); split(v1, h1, l1);
                const size_t gi = (row0 + r) * HID + colg;
                *(unsigned*)(g_h_hi + gi) = pk(h0, h1);
                *(unsigned*)(g_h_lo + gi) = pk(l0, l1);
            }
        }
    if (wn == 0) {
#pragma unroll
        for (int mi = 0; mi < 2; mi++)
#pragma unroll
            for (int nj = 0; nj < 2; nj++) {
                const int colg = nj * 8 + cq;
                const float bb0 = __ldg(bpv + colg), bb1 = __ldg(bpv + colg + 1);
#pragma unroll
                for (int hr = 0; hr < 2; hr++) {
                    const int r = wm * 32 + mi * 16 + rq + hr * 8;
                    float2 v = make_float2(axi[mi][nj][hr * 2 + 0] + bb0,
                                           axi[mi][nj][hr * 2 + 1] + bb1);
                    *(float2*)(g_xi + (row0 + r) * MD + colg) = v;
                }
            }
    }
}

// ---------- GEMM2 + fused SPD solve: y = solve(AA^T+0.1I, -xi/(t+eps)) ------
// Mainloop: gf = h@W2+b2 (M64 N256 k32). Epilogue: gf -> smem, register GJ,
// emit Y bf16 hi/lo. gf never touches DRAM.
__global__ __launch_bounds__(256, 2)
void gemm2_s(const float* __restrict__ b2v, const float* __restrict__ t) {
    extern __shared__ char smc[];
    const unsigned sb = su32(smc);
    const int tid = threadIdx.x, lane = tid & 31, w = tid >> 5;
    const int wm = w >> 2, wn = w & 3;
    const int t8 = lane >> 3, r8 = lane & 7;
    const size_t row0 = (size_t)blockIdx.x * 64;

    float acc[2][8][4] = {};

    auto cpaA = [&](int c, int s) {
        int r = tid >> 2, v = tid & 3;
        const size_t src = (row0 + r) * HID + c * 32 + v * 8;
        cpa16(sb + AHI(s) + r * RS + v * 16, g_h_hi + src);
        cpa16(sb + ALO(s) + r * RS + v * 16, g_h_lo + src);
    };
    auto cpaB = [&](int c, int s) {
#pragma unroll
        for (int i = 0; i < 4; i++) {
            int j = tid + i * 256, r = j >> 2, v = j & 3;
            const size_t src = (size_t)r * HID + c * 32 + v * 8;
            cpa16(sb + BHI(s) + r * RS + v * 16, g_W2t_hi + src);
            cpa16(sb + BLO(s) + r * RS + v * 16, g_W2t_lo + src);
        }
    };

    cpaA(0, 0); cpaB(0, 0);
    CP_COMMIT(); CP_WAIT0();
    __syncthreads();

    for (int c = 0; c < 8; c++) {
        const int s = c & 1;
        const bool more = (c + 1 < 8);
        if (more) { cpaA(c + 1, s ^ 1); cpaB(c + 1, s ^ 1); CP_COMMIT(); }
#pragma unroll
        for (int ks = 0; ks < 2; ks++) {
            const int u = ks * 2 + (t8 >> 1);
            unsigned ah[2][4], al[2][4];
#pragma unroll
            for (int mi = 0; mi < 2; mi++) {
                int m = wm * 32 + mi * 16 + (t8 & 1) * 8 + r8;
                ldm4(ah[mi], sb + AHI(s) + m * RS + u * 16);
                ldm4(al[mi], sb + ALO(s) + m * RS + u * 16);
            }
#pragma unroll
            for (int ng = 0; ng < 4; ng++) {
                unsigned bh[4], bo[4];
                int n = wn * 64 + ng * 16 + (t8 & 1) * 8 + r8;
                ldm4(bh, sb + BHI(s) + n * RS + u * 16);
                ldm4(bo, sb + BLO(s) + n * RS + u * 16);
#pragma unroll
                for (int mi = 0; mi < 2; mi++)
#pragma unroll
                    for (int o = 0; o < 2; o++) {
                        float (&A_)[4] = acc[mi][ng * 2 + o];
                        mma16816(A_, ah[mi], bh[o], bh[o + 2]);
                        mma16816(A_, ah[mi], bo[o], bo[o + 2]);
                        mma16816(A_, al[mi], bh[o], bh[o + 2]);
                    }
            }
        }
        CP_WAIT0();
        __syncthreads();
    }

    // stage gf = acc + b2 into smem [64][264] (reuses mainloop buffers)
    float* smf = (float*)smc;
    const int rq = lane >> 2, cq = (lane & 3) * 2;
#pragma unroll
    for (int mi = 0; mi < 2; mi++)
#pragma unroll
        for (int nj = 0; nj < 8; nj++) {
            const int colg = wn * 64 + nj * 8 + cq;
            const float bb0 = __ldg(b2v + colg), bb1 = __ldg(b2v + colg + 1);
#pragma unroll
            for (int hr = 0; hr < 2; hr++) {
                const int r = wm * 32 + mi * 16 + rq + hr * 8;
                smf[r * 264 + colg]     = acc[mi][nj][hr * 2 + 0] + bb0;
                smf[r * 264 + colg + 1] = acc[mi][nj][hr * 2 + 1] + bb1;
            }
        }
    __syncthreads();

    // register GJ: each half-warp solves one matrix per pass; 4 passes = 64 rows
    const int sl = lane & 15;
    const int half = lane >> 4;
    for (int pass = 0; pass < 4; pass++) {
        const int r = w * 8 + pass * 2 + half;
        const size_t grow = row0 + r;

        // a[k] = gf[grow][sl*16+k], rotated read (17-word lane stride, no conflicts)
        float a[16];
        const float* Ar = smf + r * 264 + sl * 16;
#pragma unroll
        for (int k0 = 0; k0 < 16; k0++) {
            const int kk = (k0 + sl) & 15;
            a[kk] = Ar[kk];
        }

        float g[16];
#pragma unroll
        for (int j = 0; j < 16; j++) {
            float s = (sl == j) ? 0.1f : 0.0f;
#pragma unroll
            for (int k = 0; k < 16; k++)
                s += a[k] * __shfl_sync(0xffffffffu, a[k], j, 16);
            g[j] = s;
        }

        float y = -__ldg(g_xi + grow * MD + sl) / (__ldg(t + grow) + 1e-6f);

        float diag = 1.0f;
#pragma unroll
        for (int k = 0; k < 16; k++) {
            const float piv = __shfl_sync(0xffffffffu, g[k], k, 16);
            const float yk  = __shfl_sync(0xffffffffu, y, k, 16);
            const float f   = g[k] / piv;
            if (sl == k) diag = piv;
#pragma unroll
            for (int c2 = 0; c2 < 16; c2++) {
                const float rkc = __shfl_sync(0xffffffffu, g[c2], k, 16);
                if (sl != k) g[c2] -= f * rkc;
            }
            if (sl != k) y -= f * yk;
        }
        const float yv = y / diag;

        __nv_bfloat16 bh = __float2bfloat16(yv);
        __nv_bfloat16 bo = __float2bfloat16(yv - __bfloat162float(bh));
        unsigned uh = (unsigned)*(unsigned short*)&bh;
        unsigned uo = (unsigned)*(unsigned short*)&bo;
        unsigned nh = __shfl_down_sync(0xffffffffu, uh, 1);
        unsigned no = __shfl_down_sync(0xffffffffu, uo, 1);
        if ((sl & 1) == 0) {
            *(unsigned*)(g_y_hi + grow * MD + sl) = uh | (nh << 16);
            *(unsigned*)(g_y_lo + grow * MD + sl) = uo | (no << 16);
        }
    }
}

// ---------- gemm3: out = Y @ Wl + bl (tensor, bf16 3-term). M64, N784 -------
#define G3_BH 0
#define G3_BL 25088
#define G3_YH 50176           // 64 rows x 48B padded
#define G3_YL 53248
#define SMG3  56320

__global__ __launch_bounds__(256)
void gemm3_k(const float* __restrict__ bl, float* __restrict__ out)
{
    extern __shared__ char smc[];
    const unsigned sb = su32(smc);
    const int tid = threadIdx.x, lane = tid & 31, w = tid >> 5;
    const int t8 = lane >> 3, r8 = lane & 7;
    const size_t row0 = (size_t)blockIdx.x * 64;

    // stage Wl^T hi/lo (linear) and Y hi/lo (48B-padded rows)
    for (int i = 0; i < 7; i++) {
        int j = tid + i * 256;
        if (j < 1568) {
            cpa16(sb + G3_BH + j * 16, g_Wlb_hi + j * 8);
            cpa16(sb + G3_BL + j * 16, g_Wlb_lo + j * 8);
        }
    }
    {
        int j = tid & 127, r = j >> 1, h = j & 1;
        const size_t src = (row0 + r) * MD + h * 8;
        if (tid < 128) cpa16(sb + G3_YH + r * 48 + h * 16, g_y_hi + src);
        else           cpa16(sb + G3_YL + r * 48 + h * 16, g_y_lo + src);
    }
    CP_COMMIT(); CP_WAIT0();
    __syncthreads();

    // warp w: m16 block = (w&3)*16 ; n-half = w>>2 covers 49 n8 tiles
    const int mb = (w & 3) * 16;
    const int nt0 = (w >> 2) * 49;
    const int rq = lane >> 2, cq = (lane & 3) * 2;

    unsigned ah[4], al[4];
    {
        unsigned aaddr = sb + G3_YH + (mb + (t8 & 1) * 8 + r8) * 48 + (t8 >> 1) * 16;
        ldm4(ah, aaddr);
        ldm4(al, aaddr + (G3_YL - G3_YH));
    }

    for (int nt = nt0; nt < nt0 + 49; nt++) {
        unsigned bh[2], bo[2];
        int brow = nt * 8 + r8;
        unsigned baddr = sb + G3_BH + brow * 32 + ((lane >> 3) & 1) * 16;
        ldm2(bh, baddr);
        ldm2(bo, baddr + (G3_BL - G3_BH));

        float acc[4] = {};
        mma16816bf(acc, ah, bh[0], bh[1]);
        mma16816bf(acc, ah, bo[0], bo[1]);
        mma16816bf(acc, al, bh[0], bh[1]);

        const int col = nt * 8 + cq;
        const float bb0 = __ldg(bl + col), bb1 = __ldg(bl + col + 1);
        *(float2*)(out + (row0 + mb + rq) * DD + col) =
            make_float2(acc[0] + bb0, acc[1] + bb1);
        *(float2*)(out + (row0 + mb + rq + 8) * DD + col) =
            make_float2(acc[2] + bb0, acc[3] + bb1);
    }
}

extern "C" void kernel_launch(void* const* d_in, const int* in_sizes, int n_in,
                              void* d_out, int out_size)
{
    const float* x_t = (const float*)d_in[0];
    const float* t   = (const float*)d_in[1];
    const float* W1  = (const float*)d_in[2];
    const float* b1  = (const float*)d_in[3];
    const float* W2  = (const float*)d_in[4];
    const float* b2  = (const float*)d_in[5];
    const float* Wp  = (const float*)d_in[6];
    const float* bp  = (const float*)d_in[7];
    const float* Wl  = (const float*)d_in[8];
    const float* bl  = (const float*)d_in[9];
    float* out = (float*)d_out;

    cudaFuncSetAttribute((const void*)gemm1_m, cudaFuncAttributeMaxDynamicSharedMemorySize, SMG1);
    cudaFuncSetAttribute((const void*)gemm2_s, cudaFuncAttributeMaxDynamicSharedMemorySize, SMG2);
    cudaFuncSetAttribute((const void*)gemm3_k, cudaFuncAttributeMaxDynamicSharedMemorySize, SMG3);

    prep_kernel<<<1189, 256>>>(W1, W2, Wp, Wl);
    gemm1_m<<<B_ / 64, 256, SMG1>>>(x_t, b1, bp);
    gemm2_s<<<B_ / 64, 256, SMG2>>>(b2, t);
    gemm3_k<<<B_ / 64, 256, SMG3>>>(bl, out);
}

// round 15
// speedup vs baseline: 1.0713x; 1.0713x over previous
#include <cuda_runtime.h>
#include <cuda_fp16.h>
#include <cuda_bf16.h>

#define B_  131072
#define DD  784
#define HID 256
#define MD  16
#define KP1 800  // K padded for gemm1: 25 chunks of 32
#define RS  80   // padded smem row stride (bytes) for a 32-half k-row

__device__ __align__(16) __half g_W1t_hi[HID * KP1];
__device__ __align__(16) __half g_W1t_lo[HID * KP1];
__device__ __align__(16) __half g_W2t_hi[HID * HID];
__device__ __align__(16) __half g_W2t_lo[HID * HID];
__device__ __align__(16) __half g_Wpt_hi[MD * KP1];
__device__ __align__(16) __half g_Wpt_lo[MD * KP1];
__device__ __align__(16) __nv_bfloat16 g_Wlb_hi[DD * MD];  // Wl^T [784][16] bf16 hi
__device__ __align__(16) __nv_bfloat16 g_Wlb_lo[DD * MD];
__device__ __align__(16) __nv_bfloat16 g_y_hi[(size_t)B_ * MD];
__device__ __align__(16) __nv_bfloat16 g_y_lo[(size_t)B_ * MD];
__device__ __align__(16) __half g_h_hi[(size_t)B_ * HID];
__device__ __align__(16) __half g_h_lo[(size_t)B_ * HID];
__device__ __align__(16) float g_gf[(size_t)B_ * HID];
__device__ __align__(16) float g_xi[(size_t)B_ * MD];

__device__ __forceinline__ unsigned su32(const void* p) {
    unsigned a;
    asm("{ .reg .u64 t; cvta.to.shared.u64 t, %1; cvt.u32.u64 %0, t; }" : "=r"(a) : "l"(p));
    return a;
}
__device__ __forceinline__ void ldm4(unsigned (&r)[4], unsigned addr) {
    asm volatile("ldmatrix.sync.aligned.m8n8.x4.shared.b16 {%0,%1,%2,%3}, [%4];"
                 : "=r"(r[0]), "=r"(r[1]), "=r"(r[2]), "=r"(r[3]) : "r"(addr));
}
__device__ __forceinline__ void ldm2(unsigned (&r)[2], unsigned addr) {
    asm volatile("ldmatrix.sync.aligned.m8n8.x2.shared.b16 {%0,%1}, [%2];"
                 : "=r"(r[0]), "=r"(r[1]) : "r"(addr));
}
__device__ __forceinline__ void mma16816(float (&c)[4], const unsigned (&a)[4],
                                         unsigned b0, unsigned b1) {
    asm volatile("mma.sync.aligned.m16n8k16.row.col.f32.f16.f16.f32 "
                 "{%0,%1,%2,%3}, {%4,%5,%6,%7}, {%8,%9}, {%0,%1,%2,%3};"
                 : "+f"(c[0]), "+f"(c[1]), "+f"(c[2]), "+f"(c[3])
                 : "r"(a[0]), "r"(a[1]), "r"(a[2]), "r"(a[3]), "r"(b0), "r"(b1));
}
__device__ __forceinline__ void mma16816bf(float (&c)[4], const unsigned (&a)[4],
                                           unsigned b0, unsigned b1) {
    asm volatile("mma.sync.aligned.m16n8k16.row.col.f32.bf16.bf16.f32 "
                 "{%0,%1,%2,%3}, {%4,%5,%6,%7}, {%8,%9}, {%0,%1,%2,%3};"
                 : "+f"(c[0]), "+f"(c[1]), "+f"(c[2]), "+f"(c[3])
                 : "r"(a[0]), "r"(a[1]), "r"(a[2]), "r"(a[3]), "r"(b0), "r"(b1));
}
__device__ __forceinline__ void cpa16(unsigned s, const void* g) {
    asm volatile("cp.async.cg.shared.global [%0], [%1], 16;" :: "r"(s), "l"(g));
}
#define CP_COMMIT() asm volatile("cp.async.commit_group;" ::: "memory")
#define CP_WAIT0()  asm volatile("cp.async.wait_group 0;" ::: "memory")

__device__ __forceinline__ unsigned pk(__half a, __half b) {
    return (unsigned)__half_as_ushort(a) | ((unsigned)__half_as_ushort(b) << 16);
}
__device__ __forceinline__ void split(float v, __half& h, __half& l) {
    h = __float2half_rn(v);
    l = __float2half_rn(v - __half2float(h));
}

// prep: W^T fp16 hi/lo (zero-padded K); Wl^T bf16 hi/lo
__global__ void prep_kernel(const float* __restrict__ W1, const float* __restrict__ W2,
                            const float* __restrict__ Wp, const float* __restrict__ Wl) {
    int idx = blockIdx.x * 256 + threadIdx.x;
    const int T1 = HID * KP1, T2 = HID * HID, T3 = MD * KP1, T4 = DD * MD;
    if (idx < T1) {
        int n = idx / KP1, k = idx - n * KP1;
        float v = (k < DD) ? W1[(size_t)k * HID + n] : 0.0f;
        __half h, l; split(v, h, l);
        g_W1t_hi[idx] = h; g_W1t_lo[idx] = l;
    } else if (idx < T1 + T2) {
        int j = idx - T1, n = j >> 8, k = j & 255;
        float v = W2[(size_t)k * HID + n];
        __half h, l; split(v, h, l);
        g_W2t_hi[j] = h; g_W2t_lo[j] = l;
    } else if (idx < T1 + T2 + T3) {
        int j = idx - T1 - T2, n = j / KP1, k = j - n * KP1;
        float v = (k < DD) ? Wp[(size_t)k * MD + n] : 0.0f;
        __half h, l; split(v, h, l);
        g_Wpt_hi[j] = h; g_Wpt_lo[j] = l;
    } else if (idx < T1 + T2 + T3 + T4) {
        int j = idx - T1 - T2 - T3, col = j >> 4, k = j & 15;
        float v = Wl[(size_t)k * DD + col];
        __nv_bfloat16 h = __float2bfloat16(v);
        g_Wlb_hi[j] = h;
        g_Wlb_lo[j] = __float2bfloat16(v - __bfloat162float(h));
    }
}

// smem layout per stage (51200 B): A hi 5120 | A lo 5120 | B hi 20480 | B lo 20480
#define AHI(s) ((s) * 51200)
#define ALO(s) ((s) * 51200 + 5120)
#define BHI(s) ((s) * 51200 + 10240)
#define BLO(s) ((s) * 51200 + 30720)
#define PHI(s) (102400 + (s) * 2560)
#define PLO(s) (102400 + (s) * 2560 + 1280)
#define SMG1 107520
#define SMG2 102400

// ---------- GEMM1 merged: h = relu(x@W1+b1), xi = x@Wp+bp. M64 N256 k32 -----
__global__ __launch_bounds__(256, 2)
void gemm1_m(const float* __restrict__ X, const float* __restrict__ b1v,
             const float* __restrict__ bpv) {
    extern __shared__ char smc[];
    const unsigned sb = su32(smc);
    const int tid = threadIdx.x, lane = tid & 31, w = tid >> 5;
    const int wm = w >> 2, wn = w & 3;
    const int t8 = lane >> 3, r8 = lane & 7;
    const size_t row0 = (size_t)blockIdx.x * 64;

    float acc[2][8][4] = {};
    float axi[2][2][4] = {};
    float xr[8];
    const int ar = tid >> 2, av = tid & 3;

    auto ldgA = [&](int c) {
        int col = c * 32 + av * 8;
        if (col < DD) {
            *(float4*)xr       = *(const float4*)(X + (row0 + ar) * DD + col);
            *(float4*)(xr + 4) = *(const float4*)(X + (row0 + ar) * DD + col + 4);
        } else {
#pragma unroll
            for (int i = 0; i < 8; i++) xr[i] = 0.0f;
        }
    };
    auto stsA = [&](int s) {
        __half h[8], l[8];
#pragma unroll
        for (int i = 0; i < 8; i++) split(xr[i], h[i], l[i]);
        uint4 vh, vl;
        vh.x = pk(h[0], h[1]); vh.y = pk(h[2], h[3]); vh.z = pk(h[4], h[5]); vh.w = pk(h[6], h[7]);
        vl.x = pk(l[0], l[1]); vl.y = pk(l[2], l[3]); vl.z = pk(l[4], l[5]); vl.w = pk(l[6], l[7]);
        *(uint4*)(smc + AHI(s) + ar * RS + av * 16) = vh;
        *(uint4*)(smc + ALO(s) + ar * RS + av * 16) = vl;
    };
    auto cpaB = [&](int c, int s) {
#pragma unroll
        for (int i = 0; i < 4; i++) {
            int j = tid + i * 256, r = j >> 2, v = j & 3;
            const size_t src = (size_t)r * KP1 + c * 32 + v * 8;
            cpa16(sb + BHI(s) + r * RS + v * 16, g_W1t_hi + src);
            cpa16(sb + BLO(s) + r * RS + v * 16, g_W1t_lo + src);
        }
        if (tid < 128) {
            int r = (tid & 63) >> 2, v = tid & 3;
            const size_t src = (size_t)r * KP1 + c * 32 + v * 8;
            if (tid < 64) cpa16(sb + PHI(s) + r * RS + v * 16, g_Wpt_hi + src);
            else          cpa16(sb + PLO(s) + r * RS + v * 16, g_Wpt_lo + src);
        }
    };

    ldgA(0); stsA(0); cpaB(0, 0);
    CP_COMMIT(); CP_WAIT0();
    __syncthreads();

    for (int c = 0; c < 25; c++) {
        const int s = c & 1;
        const bool more = (c + 1 < 25);
        if (more) { ldgA(c + 1); cpaB(c + 1, s ^ 1); CP_COMMIT(); }
#pragma unroll
        for (int ks = 0; ks < 2; ks++) {
            const int u = ks * 2 + (t8 >> 1);
            unsigned ah[2][4], al[2][4];
#pragma unroll
            for (int mi = 0; mi < 2; mi++) {
                int m = wm * 32 + mi * 16 + (t8 & 1) * 8 + r8;
                ldm4(ah[mi], sb + AHI(s) + m * RS + u * 16);
                ldm4(al[mi], sb + ALO(s) + m * RS + u * 16);
            }
#pragma unroll
            for (int ng = 0; ng < 4; ng++) {
                unsigned bh[4], bo[4];
                int n = wn * 64 + ng * 16 + (t8 & 1) * 8 + r8;
                ldm4(bh, sb + BHI(s) + n * RS + u * 16);
                ldm4(bo, sb + BLO(s) + n * RS + u * 16);
#pragma unroll
                for (int mi = 0; mi < 2; mi++)
#pragma unroll
                    for (int o = 0; o < 2; o++) {
                        float (&A_)[4] = acc[mi][ng * 2 + o];
                        mma16816(A_, ah[mi], bh[o], bh[o + 2]);
                        mma16816(A_, ah[mi], bo[o], bo[o + 2]);
                        mma16816(A_, al[mi], bh[o], bh[o + 2]);
                    }
            }
            if (wn == 0) {
                unsigned ph[4], po[4];
                int n = (t8 & 1) * 8 + r8;
                ldm4(ph, sb + PHI(s) + n * RS + u * 16);
                ldm4(po, sb + PLO(s) + n * RS + u * 16);
#pragma unroll
                for (int mi = 0; mi < 2; mi++)
#pragma unroll
                    for (int nj = 0; nj < 2; nj++) {
                        mma16816(axi[mi][nj], ah[mi], ph[nj], ph[nj + 2]);
                        mma16816(axi[mi][nj], ah[mi], po[nj], po[nj + 2]);
                        mma16816(axi[mi][nj], al[mi], ph[nj], ph[nj + 2]);
                    }
            }
        }
        if (more) stsA(s ^ 1);
        CP_WAIT0();
        __syncthreads();
    }

    const int rq = lane >> 2, cq = (lane & 3) * 2;
#pragma unroll
    for (int mi = 0; mi < 2; mi++)
#pragma unroll
        for (int nj = 0; nj < 8; nj++) {
            const int colg = wn * 64 + nj * 8 + cq;
            const float bb0 = __ldg(b1v + colg), bb1 = __ldg(b1v + colg + 1);
#pragma unroll
            for (int hr = 0; hr < 2; hr++) {
                const int r = wm * 32 + mi * 16 + rq + hr * 8;
                float v0 = fmaxf(acc[mi][nj][hr * 2 + 0] + bb0, 0.0f);
                float v1 = fmaxf(acc[mi][nj][hr * 2 + 1] + bb1, 0.0f);
                __half h0, l0, h1, l1;
                split(v0, h0, l0); split(v1, h1, l1);
                const size_t gi = (row0 + r) * HID + colg;
                *(unsigned*)(g_h_hi + gi) = pk(h0, h1);
                *(unsigned*)(g_h_lo + gi) = pk(l0, l1);
            }
        }
    if (wn == 0) {
#pragma unroll
        for (int mi = 0; mi < 2; mi++)
#pragma unroll
            for (int nj = 0; nj < 2; nj++) {
                const int colg = nj * 8 + cq;
                const float bb0 = __ldg(bpv + colg), bb1 = __ldg(bpv + colg + 1);
#pragma unroll
                for (int hr = 0; hr < 2; hr++) {
                    const int r = wm * 32 + mi * 16 + rq + hr * 8;
                    float2 v = make_float2(axi[mi][nj][hr * 2 + 0] + bb0,
                                           axi[mi][nj][hr * 2 + 1] + bb1);
                    *(float2*)(g_xi + (row0 + r) * MD + colg) = v;
                }
            }
    }
}

// ---------- GEMM2 merged: gf = h@W2+b2. M64 N256 k32 -----------------------
__global__ __launch_bounds__(256, 2)
void gemm2_m(const float* __restrict__ b2v) {
    extern __shared__ char smc[];
    const unsigned sb = su32(smc);
    const int tid = threadIdx.x, lane = tid & 31, w = tid >> 5;
    const int wm = w >> 2, wn = w & 3;
    const int t8 = lane >> 3, r8 = lane & 7;
    const size_t row0 = (size_t)blockIdx.x * 64;

    float acc[2][8][4] = {};

    auto cpaA = [&](int c, int s) {
        int r = tid >> 2, v = tid & 3;
        const size_t src = (row0 + r) * HID + c * 32 + v * 8;
        cpa16(sb + AHI(s) + r * RS + v * 16, g_h_hi + src);
        cpa16(sb + ALO(s) + r * RS + v * 16, g_h_lo + src);
    };
    auto cpaB = [&](int c, int s) {
#pragma unroll
        for (int i = 0; i < 4; i++) {
            int j = tid + i * 256, r = j >> 2, v = j & 3;
            const size_t src = (size_t)r * HID + c * 32 + v * 8;
            cpa16(sb + BHI(s) + r * RS + v * 16, g_W2t_hi + src);
            cpa16(sb + BLO(s) + r * RS + v * 16, g_W2t_lo + src);
        }
    };

    cpaA(0, 0); cpaB(0, 0);
    CP_COMMIT(); CP_WAIT0();
    __syncthreads();

    for (int c = 0; c < 8; c++) {
        const int s = c & 1;
        const bool more = (c + 1 < 8);
        if (more) { cpaA(c + 1, s ^ 1); cpaB(c + 1, s ^ 1); CP_COMMIT(); }
#pragma unroll
        for (int ks = 0; ks < 2; ks++) {
            const int u = ks * 2 + (t8 >> 1);
            unsigned ah[2][4], al[2][4];
#pragma unroll
            for (int mi = 0; mi < 2; mi++) {
                int m = wm * 32 + mi * 16 + (t8 & 1) * 8 + r8;
                ldm4(ah[mi], sb + AHI(s) + m * RS + u * 16);
                ldm4(al[mi], sb + ALO(s) + m * RS + u * 16);
            }
#pragma unroll
            for (int ng = 0; ng < 4; ng++) {
                unsigned bh[4], bo[4];
                int n = wn * 64 + ng * 16 + (t8 & 1) * 8 + r8;
                ldm4(bh, sb + BHI(s) + n * RS + u * 16);
                ldm4(bo, sb + BLO(s) + n * RS + u * 16);
#pragma unroll
                for (int mi = 0; mi < 2; mi++)
#pragma unroll
                    for (int o = 0; o < 2; o++) {
                        float (&A_)[4] = acc[mi][ng * 2 + o];
                        mma16816(A_, ah[mi], bh[o], bh[o + 2]);
                        mma16816(A_, ah[mi], bo[o], bo[o + 2]);
                        mma16816(A_, al[mi], bh[o], bh[o + 2]);
                    }
            }
        }
        CP_WAIT0();
        __syncthreads();
    }

    const int rq = lane >> 2, cq = (lane & 3) * 2;
#pragma unroll
    for (int mi = 0; mi < 2; mi++)
#pragma unroll
        for (int nj = 0; nj < 8; nj++) {
            const int colg = wn * 64 + nj * 8 + cq;
            const float bb0 = __ldg(b2v + colg), bb1 = __ldg(b2v + colg + 1);
#pragma unroll
            for (int hr = 0; hr < 2; hr++) {
                const int r = wm * 32 + mi * 16 + rq + hr * 8;
                float2 v = make_float2(acc[mi][nj][hr * 2 + 0] + bb0,
                                       acc[mi][nj][hr * 2 + 1] + bb1);
                *(float2*)(g_gf + (row0 + r) * HID + colg) = v;
            }
        }
}

// ---------- solve: register GJ; emit Y as bf16 hi/lo ------------------------
__global__ __launch_bounds__(256)
void solve_k(const float* __restrict__ t)
{
    const int tid = threadIdx.x, w = tid >> 5, lane = tid & 31;
    const int sl = lane & 15;
    const int half = lane >> 4;
    const size_t row0 = (size_t)blockIdx.x * 32;

    for (int pass = 0; pass < 2; pass++) {
        const int r = w * 4 + pass * 2 + half;
        const size_t grow = row0 + r;

        float a[16];
        const float4* ap = (const float4*)(g_gf + grow * HID + sl * 16);
        float4 q0 = ap[0], q1 = ap[1], q2 = ap[2], q3 = ap[3];
        a[0]=q0.x; a[1]=q0.y; a[2]=q0.z; a[3]=q0.w;
        a[4]=q1.x; a[5]=q1.y; a[6]=q1.z; a[7]=q1.w;
        a[8]=q2.x; a[9]=q2.y; a[10]=q2.z; a[11]=q2.w;
        a[12]=q3.x; a[13]=q3.y; a[14]=q3.z; a[15]=q3.w;

        float g[16];
#pragma unroll
        for (int j = 0; j < 16; j++) {
            float s = (sl == j) ? 0.1f : 0.0f;
#pragma unroll
            for (int k = 0; k < 16; k++)
                s += a[k] * __shfl_sync(0xffffffffu, a[k], j, 16);
            g[j] = s;
        }

        float y = -__ldg(g_xi + grow * MD + sl) / (__ldg(t + grow) + 1e-6f);

        float diag = 1.0f;
#pragma unroll
        for (int k = 0; k < 16; k++) {
            const float piv = __shfl_sync(0xffffffffu, g[k], k, 16);
            const float yk  = __shfl_sync(0xffffffffu, y, k, 16);
            const float f   = g[k] / piv;
            if (sl == k) diag = piv;
#pragma unroll
            for (int c = 0; c < 16; c++) {
                const float rkc = __shfl_sync(0xffffffffu, g[c], k, 16);
                if (sl != k) g[c] -= f * rkc;
            }
            if (sl != k) y -= f * yk;
        }
        const float yv = y / diag;

        __nv_bfloat16 bh = __float2bfloat16(yv);
        __nv_bfloat16 bo = __float2bfloat16(yv - __bfloat162float(bh));
        unsigned uh = (unsigned)*(unsigned short*)&bh;
        unsigned uo = (unsigned)*(unsigned short*)&bo;
        unsigned nh = __shfl_down_sync(0xffffffffu, uh, 1);
        unsigned no = __shfl_down_sync(0xffffffffu, uo, 1);
        if ((sl & 1) == 0) {
            *(unsigned*)(g_y_hi + grow * MD + sl) = uh | (nh << 16);
            *(unsigned*)(g_y_lo + grow * MD + sl) = uo | (no << 16);
        }
    }
}

// ---------- gemm3: out = Y @ Wl + bl (tensor, bf16 3-term). M128, N784 ------
#define G3_BH 0
#define G3_BL 25088
#define G3_YH 50176           // 128 rows x 48B padded
#define G3_YL 56320
#define SMG3  62464

__global__ __launch_bounds__(256)
void gemm3_k(const float* __restrict__ bl, float* __restrict__ out)
{
    extern __shared__ char smc[];
    const unsigned sb = su32(smc);
    const int tid = threadIdx.x, lane = tid & 31, w = tid >> 5;
    const int t8 = lane >> 3, r8 = lane & 7;
    const size_t row0 = (size_t)blockIdx.x * 128;

    // stage Wl^T hi/lo (linear) and Y hi/lo (48B-padded rows, 128 rows)
    for (int i = 0; i < 7; i++) {
        int j = tid + i * 256;
        if (j < 1568) {
            cpa16(sb + G3_BH + j * 16, g_Wlb_hi + j * 8);
            cpa16(sb + G3_BL + j * 16, g_Wlb_lo + j * 8);
        }
    }
    {
        int r = tid >> 1, hf = tid & 1;
        const size_t src = (row0 + r) * MD + hf * 8;
        cpa16(sb + G3_YH + r * 48 + hf * 16, g_y_hi + src);
        cpa16(sb + G3_YL + r * 48 + hf * 16, g_y_lo + src);
    }
    CP_COMMIT(); CP_WAIT0();
    __syncthreads();

    // warp w owns m16 block w*16; each warp covers all 98 n8 tiles
    const int mb = w * 16;
    const int rq = lane >> 2, cq = (lane & 3) * 2;

    unsigned ah[4], al[4];
    {
        unsigned aaddr = sb + G3_YH + (mb + (t8 & 1) * 8 + r8) * 48 + (t8 >> 1) * 16;
        ldm4(ah, aaddr);
        ldm4(al, aaddr + (G3_YL - G3_YH));
    }

    for (int nt = 0; nt < 98; nt++) {
        unsigned bh[2], bo[2];
        int brow = nt * 8 + r8;
        unsigned baddr = sb + G3_BH + brow * 32 + ((lane >> 3) & 1) * 16;
        ldm2(bh, baddr);
        ldm2(bo, baddr + (G3_BL - G3_BH));

        float acc[4] = {};
        mma16816bf(acc, ah, bh[0], bh[1]);
        mma16816bf(acc, ah, bo[0], bo[1]);
        mma16816bf(acc, al, bh[0], bh[1]);

        const int col = nt * 8 + cq;
        const float bb0 = __ldg(bl + col), bb1 = __ldg(bl + col + 1);
        *(float2*)(out + (row0 + mb + rq) * DD + col) =
            make_float2(acc[0] + bb0, acc[1] + bb1);
        *(float2*)(out + (row0 + mb + rq + 8) * DD + col) =
            make_float2(acc[2] + bb0, acc[3] + bb1);
    }
}

extern "C" void kernel_launch(void* const* d_in, const int* in_sizes, int n_in,
                              void* d_out, int out_size)
{
    const float* x_t = (const float*)d_in[0];
    const float* t   = (const float*)d_in[1];
    const float* W1  = (const float*)d_in[2];
    const float* b1  = (const float*)d_in[3];
    const float* W2  = (const float*)d_in[4];
    const float* b2  = (const float*)d_in[5];
    const float* Wp  = (const float*)d_in[6];
    const float* bp  = (const float*)d_in[7];
    const float* Wl  = (const float*)d_in[8];
    const float* bl  = (const float*)d_in[9];
    float* out = (float*)d_out;

    cudaFuncSetAttribute((const void*)gemm1_m, cudaFuncAttributeMaxDynamicSharedMemorySize, SMG1);
    cudaFuncSetAttribute((const void*)gemm2_m, cudaFuncAttributeMaxDynamicSharedMemorySize, SMG2);
    cudaFuncSetAttribute((const void*)gemm3_k, cudaFuncAttributeMaxDynamicSharedMemorySize, SMG3);

    // total prep elems: HID*KP1 + HID*HID + MD*KP1 + DD*MD
    const int prep_total = HID * KP1 + HID * HID + MD * KP1 + DD * MD;
    prep_kernel<<<(prep_total + 255) / 256, 256>>>(W1, W2, Wp, Wl);
    gemm1_m<<<B_ / 64, 256, SMG1>>>(x_t, b1, bp);
    gemm2_m<<<B_ / 64, 256, SMG2>>>(b2);
    solve_k<<<B_ / 32, 256>>>(t);
    gemm3_k<<<B_ / 128, 256, SMG3>>>(bl, out);
}